// round 5
// baseline (speedup 1.0000x reference)
#include <cuda_runtime.h>
#include <cstdint>

#define HH 2160
#define WW 3840
#define NS 512
#define ADJ_ELEMS (NS * NS)

#define TILE_W   128
#define TILE_H   48
#define ROWS_PW  6              // rows per warp (8 warps x 6 = 48)
#define CHUNK_H  16             // privatization chunk: 128 x 16
#define NCHUNK_X (WW / TILE_W)  // 30
#define NCOPY    4096           // padded (real copies: 135*30 = 4050)

// Privatized packed histogram: g_hist[bin * NCOPY + copy]
//   bits [0:7)  count, [7:21) sum of dx (0..127), [21:32) sum of dy (0..15)
__device__ unsigned int g_hist[NS * NCOPY];   // 8 MB, L2-resident

// ---------------------------------------------------------------------------
// Kernel 1: zero adjacency (1MB) + histogram (8MB), vectorized.
// ---------------------------------------------------------------------------
__global__ void zero_kernel(uint4* __restrict__ adj4) {
    int idx = blockIdx.x * blockDim.x + threadIdx.x;   // 589824 x 16B
    if (idx < ADJ_ELEMS / 4)
        adj4[idx] = make_uint4(0u, 0u, 0u, 0u);
    else
        ((uint4*)g_hist)[idx - ADJ_ELEMS / 4] = make_uint4(0u, 0u, 0u, 0u);
}

// ---------------------------------------------------------------------------
// Kernel 2: main scan. 256 threads; warp w owns a 128(x) x 6(y) strip,
// lane l owns 4 consecutive pixels per row (one int4 load); the "down" row
// is carried into the next iteration's "self" (halves image loads).
//
// Centroids: ONE fire-and-forget u32 red.add per pixel into the per-chunk
// histogram copy (copy = (yg/16)*30 + bx; unique per chunk -> no cross-block
// same-address contention). No smem, no __syncthreads.
// Adjacency: idempotent __stcg 1.0f stores; borders replicate -> equal -> skip.
// ---------------------------------------------------------------------------
__global__ __launch_bounds__(256) void main_kernel(const int* __restrict__ seg,
                                                   float* __restrict__ adj) {
    const int t    = threadIdx.x;
    const int lane = t & 31;
    const int wrp  = t >> 5;                        // 0..7
    const int bx   = blockIdx.x;
    const int xg   = bx * TILE_W + lane * 4;
    const int ys   = blockIdx.y * TILE_H + wrp * ROWS_PW;

    const int* rowp = seg + (size_t)ys * WW + xg;
    int4 self = *(const int4*)rowp;

#pragma unroll
    for (int r = 0; r < ROWS_PW; ++r) {
        const int yg = ys + r;

        int4 dn;
        if (yg + 1 < HH) dn = *(const int4*)(rowp + WW);
        else             dn = self;                  // replicate at y edge

        // Right neighbor of element 3 = next lane's element 0.
        int nr = __shfl_down_sync(0xffffffffu, self.x, 1);
        if (lane == 31)
            nr = (xg + 4 < WW) ? rowp[4] : self.w;   // replicate at x edge

        const int sv[4] = {self.x, self.y, self.z, self.w};
        const int rv[4] = {self.y, self.z, self.w, nr};
        const int dv[4] = {dn.x, dn.y, dn.z, dn.w};

        const int copy = (yg >> 4) * NCHUNK_X + bx;
        const unsigned int base_val = 1u | ((unsigned int)(yg & (CHUNK_H - 1)) << 21);

#pragma unroll
        for (int j = 0; j < 4; ++j) {
            const int s = sv[j];
            const unsigned int dx = (unsigned int)(lane * 4 + j);
            atomicAdd(&g_hist[s * NCOPY + copy], base_val + (dx << 7));  // RED.u32
            const int rowb = s * NS;
            if (s != rv[j]) __stcg(&adj[rowb + rv[j]], 1.0f);
            if (s != dv[j]) __stcg(&adj[rowb + dv[j]], 1.0f);
        }

        rowp += WW;
        self = dn;
    }
}

// ---------------------------------------------------------------------------
// Kernel 3: reduce per-chunk copies -> centers. One block per bin,
// coalesced reads over the copy dimension.
// ---------------------------------------------------------------------------
__global__ __launch_bounds__(256) void centers_kernel(float* __restrict__ out) {
    const int s = blockIdx.x;
    const int t = threadIdx.x;

    unsigned int cnt = 0u;
    unsigned long long sx = 0ULL, sy = 0ULL;

#pragma unroll
    for (int k = t; k < NCOPY; k += 256) {          // 16 coalesced iters
        const unsigned int v = g_hist[s * NCOPY + k];
        const unsigned int c  = v & 127u;
        const unsigned int dx = (v >> 7) & 0x3FFFu;
        const unsigned int dy = v >> 21;
        cnt += c;
        // chunk origin from copy index (padding k>=4050 has c==0 -> no-op)
        const unsigned int cx = (unsigned int)(k % NCHUNK_X);
        const unsigned int cy = (unsigned int)(k / NCHUNK_X);
        sx += (unsigned long long)dx + (unsigned long long)c * (cx * TILE_W);
        sy += (unsigned long long)dy + (unsigned long long)c * (cy * CHUNK_H);
    }

    // block reduction (3 values)
    __shared__ unsigned long long sh[3][8];
#pragma unroll
    for (int off = 16; off > 0; off >>= 1) {
        cnt += __shfl_down_sync(0xffffffffu, cnt, off);
        sx  += __shfl_down_sync(0xffffffffu, sx, off);
        sy  += __shfl_down_sync(0xffffffffu, sy, off);
    }
    if ((t & 31) == 0) {
        sh[0][t >> 5] = cnt; sh[1][t >> 5] = sx; sh[2][t >> 5] = sy;
    }
    __syncthreads();
    if (t == 0) {
        unsigned long long C = 0, X = 0, Y = 0;
#pragma unroll
        for (int w = 0; w < 8; ++w) { C += sh[0][w]; X += sh[1][w]; Y += sh[2][w]; }
        const double c = (double)C;
        out[ADJ_ELEMS + 2 * s + 0] = (float)((double)X / c);
        out[ADJ_ELEMS + 2 * s + 1] = (float)((double)Y / c);
    }
}

extern "C" void kernel_launch(void* const* d_in, const int* in_sizes, int n_in,
                              void* d_out, int out_size) {
    const int* seg = (const int*)d_in[0];
    float* out = (float*)d_out;

    // (1MB + 8MB) / 16B = 589824 threads
    zero_kernel<<<(ADJ_ELEMS / 4 + NS * NCOPY / 4 + 255) / 256, 256>>>((uint4*)out);

    dim3 grid(WW / TILE_W, HH / TILE_H);   // 30 x 45 = 1350 blocks
    main_kernel<<<grid, 256>>>(seg, out);

    centers_kernel<<<NS, 256>>>(out);
}

// round 6
// speedup vs baseline: 1.3077x; 1.3077x over previous
#include <cuda_runtime.h>
#include <cstdint>

#define HH 2160
#define WW 3840
#define NS 512
#define ADJ_ELEMS (NS * NS)

#define TILE_W  128
#define TILE_H  48
#define CHUNK_H 16
#define NCHUNK  (TILE_H / CHUNK_H)   // 3

// Global accumulators: g_a[s] = (cnt << 40) | sum_y ; g_b[s] = sum_x
__device__ unsigned long long g_a[NS];
__device__ unsigned long long g_b[NS];

// ---------------------------------------------------------------------------
// Kernel 1: zero adjacency region (vectorized) + global accumulators.
// ---------------------------------------------------------------------------
__global__ void zero_kernel(float4* __restrict__ out) {
    int idx = blockIdx.x * blockDim.x + threadIdx.x;   // 65536 float4 = 1MB
    out[idx] = make_float4(0.f, 0.f, 0.f, 0.f);
    if (idx < NS) { g_a[idx] = 0ULL; g_b[idx] = 0ULL; }
}

// ---------------------------------------------------------------------------
// Kernel 2: main scan, WARP-SPECIALIZED so the L1tex (STG) pipe and the
// shared-atomic pipe run as disjoint instruction streams.
//
//  Warps 0..7  (A): adjacency only. Warp a owns a 128x6 strip; lane l owns
//     4 px/row via int4, "down" row carried forward. 2 idempotent __stcg/px.
//     No barriers, no smem.
//  Warps 8..15 (B): centroid histogram only. Re-loads the tile (L2-hit).
//     Per 16-row chunk, B-warp b handles rows 2b,2b+1; ONE packed-u32
//     shared atomicAdd per px:  cnt[0:7) | sum_dy[7:18) | sum_dx[18:32).
//     Chunk flush under a named barrier (id 1, 256 threads) private to B.
//     Block totals flushed with 2 u64 REDG per bin at the end.
// ---------------------------------------------------------------------------
__global__ __launch_bounds__(512) void main_kernel(const int* __restrict__ seg,
                                                   float* __restrict__ adj) {
    __shared__ unsigned int hist[NS];
    const int t    = threadIdx.x;
    const int lane = t & 31;
    const int wrp  = t >> 5;
    const int x0   = blockIdx.x * TILE_W;
    const int y0   = blockIdx.y * TILE_H;
    const int xg   = x0 + lane * 4;

    if (wrp < 8) {
        // ---------------- Family A: adjacency stores ----------------
        const int ys = y0 + wrp * 6;
        const int* rowp = seg + (size_t)ys * WW + xg;
        int4 self = *(const int4*)rowp;

#pragma unroll
        for (int r = 0; r < 6; ++r) {
            const int yg = ys + r;
            int4 dn;
            if (yg + 1 < HH) dn = *(const int4*)(rowp + WW);
            else             dn = self;                 // replicate at y edge

            int nr = __shfl_down_sync(0xffffffffu, self.x, 1);
            if (lane == 31)
                nr = (xg + 4 < WW) ? rowp[4] : self.w;  // replicate at x edge

            const int sv[4] = {self.x, self.y, self.z, self.w};
            const int rv[4] = {self.y, self.z, self.w, nr};
            const int dv[4] = {dn.x, dn.y, dn.z, dn.w};
#pragma unroll
            for (int j = 0; j < 4; ++j) {
                const int s = sv[j];
                const int rowb = s * NS;
                if (s != rv[j]) __stcg(&adj[rowb + rv[j]], 1.0f);
                if (s != dv[j]) __stcg(&adj[rowb + dv[j]], 1.0f);
            }
            rowp += WW;
            self = dn;
        }
    } else {
        // ---------------- Family B: centroid histogram ----------------
        const int b  = wrp - 8;            // 0..7
        const int bt = t - 256;            // 0..255 : B-local thread id
        // zero hist (512 words / 256 threads)
        hist[bt] = 0u; hist[bt + 256] = 0u;

        unsigned int cnt0 = 0u, sx0 = 0u, sy0 = 0u;   // bin bt
        unsigned int cnt1 = 0u, sx1 = 0u, sy1 = 0u;   // bin bt+256
        asm volatile("bar.sync 1, 256;" ::: "memory");

#pragma unroll
        for (int c = 0; c < NCHUNK; ++c) {
            const int cy0 = y0 + c * CHUNK_H;
#pragma unroll
            for (int rr = 0; rr < 2; ++rr) {
                const int dy = 2 * b + rr;
                const int4 v = *(const int4*)(seg + (size_t)(cy0 + dy) * WW + xg);
                const unsigned int dy_pack = 1u | ((unsigned int)dy << 7);
                const int sv[4] = {v.x, v.y, v.z, v.w};
#pragma unroll
                for (int j = 0; j < 4; ++j) {
                    const unsigned int dx = (unsigned int)(lane * 4 + j);
                    atomicAdd(&hist[sv[j]], dy_pack + (dx << 18));
                }
            }
            asm volatile("bar.sync 1, 256;" ::: "memory");
            // flush chunk: thread bt owns bins bt and bt+256
            {
                const unsigned int v0 = hist[bt];
                const unsigned int v1 = hist[bt + 256];
                hist[bt] = 0u; hist[bt + 256] = 0u;
                const unsigned int c0 = v0 & 127u, c1 = v1 & 127u;
                cnt0 += c0; sy0 += ((v0 >> 7) & 0x7FFu) + c0 * (unsigned int)cy0;
                sx0 += v0 >> 18;
                cnt1 += c1; sy1 += ((v1 >> 7) & 0x7FFu) + c1 * (unsigned int)cy0;
                sx1 += v1 >> 18;
            }
            asm volatile("bar.sync 1, 256;" ::: "memory");
        }

        // block flush: 2 u64 REDG per owned bin
        atomicAdd(&g_a[bt], ((unsigned long long)cnt0 << 40) | (unsigned long long)sy0);
        atomicAdd(&g_b[bt], (unsigned long long)sx0 +
                            (unsigned long long)cnt0 * (unsigned long long)x0);
        atomicAdd(&g_a[bt + 256], ((unsigned long long)cnt1 << 40) | (unsigned long long)sy1);
        atomicAdd(&g_b[bt + 256], (unsigned long long)sx1 +
                                  (unsigned long long)cnt1 * (unsigned long long)x0);
    }
}

// ---------------------------------------------------------------------------
// Kernel 3: centers[s] = (sum_x / cnt, sum_y / cnt)
// ---------------------------------------------------------------------------
__global__ void centers_kernel(float* __restrict__ out) {
    int s = blockIdx.x * blockDim.x + threadIdx.x;
    if (s < NS) {
        const unsigned long long a = g_a[s];
        const double c  = (double)(a >> 40);
        const double sy = (double)(a & ((1ULL << 40) - 1ULL));
        const double sx = (double)g_b[s];
        out[ADJ_ELEMS + 2 * s + 0] = (float)(sx / c);
        out[ADJ_ELEMS + 2 * s + 1] = (float)(sy / c);
    }
}

extern "C" void kernel_launch(void* const* d_in, const int* in_sizes, int n_in,
                              void* d_out, int out_size) {
    const int* seg = (const int*)d_in[0];
    float* out = (float*)d_out;

    zero_kernel<<<ADJ_ELEMS / 4 / 256, 256>>>((float4*)out);

    dim3 grid(WW / TILE_W, HH / TILE_H);   // 30 x 45 = 1350 blocks
    main_kernel<<<grid, 512>>>(seg, out);

    centers_kernel<<<1, NS>>>(out);
}